// round 12
// baseline (speedup 1.0000x reference)
#include <cuda_runtime.h>
#include <cuda_bf16.h>
#include <math.h>

// ---------------- Problem constants ----------------
#define NATOM 2000
#define MNB   12
#define NM    24000        // NATOM*MNB edges
#define AF    64
#define BFD   41
#define PAS   832          // per-atom output stride (806 valid cols)
#define XI0   468          // aligned base of x_i section in g_pa
#define WA0   678          // base of Wa (3-body base) section in g_pa
#define OCV   466          // per-edge valid cols: 128 h | 82 he | 128 P | 128 Q
#define OCP   468          // padded row stride
#define WSE   512          // edge weight col stride
#define KPE   22           // edge K pairs (K=41 padded to 44)
#define KPE2  11
#define KPA   32           // atom K pairs (K=64)
#define KPA2  16
#define NCR   64
#define NEL   (NM * BFD)   // 984000 edge-feature elements

// ---------------- Device scratch ----------------
__device__ float  g_x[NATOM * AF];
__device__ float  g_e[NEL];
__device__ float  g_pa[NATOM * PAS];
__device__ float  g_hpq[NM * OCP];
__device__ float  g_total[NATOM * AF];
__device__ float  g_t3[NATOM * AF];
__device__ float  g_y[NATOM * 128];
__device__ float2 g_W1p[3 * KPA * PAS];
__device__ float  g_b1[3 * PAS];
__device__ float2 g_We2p[3 * KPE * WSE];
__device__ float  g_We[92 * 64];
__device__ float  g_bn[1024];
__device__ float  g_part[400 * 512];

// ---------------- Math helpers ----------------
__device__ __forceinline__ float spf(float x) {           // softplus
    return fmaxf(x, 0.f) + __logf(1.f + __expf(-fabsf(x)));
}
__device__ __forceinline__ float sigf(float x) {          // sigmoid
    return __fdividef(1.f, 1.f + __expf(-x));
}
__device__ __forceinline__ void fma2(unsigned long long& d, unsigned long long a, unsigned long long b) {
    asm("fma.rn.f32x2 %0, %1, %2, %0;" : "+l"(d) : "l"(a), "l"(b));
}
__device__ __forceinline__ float lohi(unsigned long long a) {
    return __uint_as_float((unsigned)a) + __uint_as_float((unsigned)(a >> 32));
}

// ---------------- Weight value maps ----------------
// fcW (3,128,169): [0,64)=x_i  [64,128)=x_j  [128,169)=e
// eW  (3, 82,169): same split
// W3  (3,128,274): Wa[0,64) Wj[64,128) Wl[128,192) Wij[192,233) Wil[233,274)
__device__ __forceinline__ float wpe(const float* fcW, const float* eW, const float* W3,
                                     int L, int k, int c) {
    if (k >= 41 || c >= OCV) return 0.f;
    if (c < 128) return fcW[(L * 128 + c) * 169 + 128 + k];
    if (c < 210) return eW[(L * 82 + c - 128) * 169 + 128 + k];
    if (c < 338) return W3[(L * 128 + c - 210) * 274 + 192 + k];   // Wij
    return W3[(L * 128 + c - 338) * 274 + 233 + k];                // Wil
}
__device__ __forceinline__ float wpa(const float* fcW, const float* eW, const float* W3,
                                     int L, int k, int o) {
    if (o < 128) return fcW[(L * 128 + o) * 169 + 64 + k];          // h:  x_j
    if (o < 210) return eW[(L * 82 + o - 128) * 169 + 64 + k];      // he: x_j
    if (o < 338) return W3[(L * 128 + o - 210) * 274 + 64 + k];     // Wj
    if (o < 466) return W3[(L * 128 + o - 338) * 274 + 128 + k];    // Wl
    if (o < XI0) return 0.f;
    if (o < XI0 + 128) return fcW[(L * 128 + o - XI0) * 169 + k];   // h:  x_i
    if (o < XI0 + 210) return eW[(L * 82 + o - XI0 - 128) * 169 + k]; // he: x_i
    if (o < WA0)       return 0.f;
    if (o < WA0 + 128) return W3[(L * 128 + o - WA0) * 274 + k];    // Wa
    return 0.f;
}

__global__ void k_pack(const float* __restrict__ fcW, const float* __restrict__ eW,
                       const float* __restrict__ W3, const float* __restrict__ fcb,
                       const float* __restrict__ eb, const float* __restrict__ b3,
                       const float* __restrict__ embW, const float* __restrict__ nbr) {
    int i = blockIdx.x * 256 + threadIdx.x;
    const int R0 = 3 * KPE * WSE;
    if (i < R0) {
        int L = i / (KPE * WSE); int r = i % (KPE * WSE);
        int kp = r / WSE, c = r % WSE;
        g_We2p[i] = make_float2(wpe(fcW, eW, W3, L, 2 * kp, c),
                                wpe(fcW, eW, W3, L, 2 * kp + 1, c));
        return;
    }
    i -= R0;
    const int R1 = 3 * KPA * PAS;
    if (i < R1) {
        int L = i / (KPA * PAS); int r = i % (KPA * PAS);
        int kp = r / PAS, o = r % PAS;
        g_W1p[i] = make_float2(wpa(fcW, eW, W3, L, 2 * kp, o),
                               wpa(fcW, eW, W3, L, 2 * kp + 1, o));
        return;
    }
    i -= R1;
    const int R2 = 3 * PAS;
    if (i < R2) {
        int L = i / PAS, o = i % PAS;
        float v = 0.f;
        if (o >= XI0 && o < XI0 + 128)            v = fcb[L * 128 + o - XI0];
        else if (o >= XI0 + 128 && o < XI0 + 210) v = eb[L * 82 + o - XI0 - 128];
        else if (o >= WA0 && o < WA0 + 128)       v = b3[L * 128 + o - WA0];
        g_b1[i] = v;
        return;
    }
    i -= R2;
    if (i < 92 * 64) { int k = i / 64, o = i % 64; g_We[i] = embW[o * 92 + k]; return; }
    i -= 92 * 64;
    if (i < NEL) g_e[i] = nbr[i];
}

// ---------------- Embedding ----------------
__global__ __launch_bounds__(64) void k_emb(const float* __restrict__ af, const float* __restrict__ eb) {
    __shared__ float sa[16 * 92];
    int n0 = blockIdx.x * 16, t = threadIdx.x;
    for (int i = t; i < 16 * 92; i += 64) sa[i] = af[n0 * 92 + i];
    __syncthreads();
    float acc[16]; float b = eb[t];
#pragma unroll
    for (int r = 0; r < 16; r++) acc[r] = b;
    for (int k = 0; k < 92; k++) {
        float w = g_We[k * 64 + t];
#pragma unroll
        for (int r = 0; r < 16; r++) acc[r] = fmaf(sa[r * 92 + k], w, acc[r]);
    }
#pragma unroll
    for (int r = 0; r < 16; r++) g_x[(n0 + r) * AF + t] = acc[r];
}

// ---------------- Per-atom GEMM: g_pa = x @ W1p + b1 ----------------
// 128 threads (16x, 8y), thread tile 8 rows x 4 cols, block tile 64x64.
__global__ __launch_bounds__(128, 4) void k_pa(int L) {
    __shared__ __align__(16) float  sX[64 * 64];
    __shared__ __align__(16) float2 sW[KPA * 64];       // permuted: (kp2*64 + (c&3)*16 + c>>2)*2 + half
    int rowBase = blockIdx.x * 64, colBase = blockIdx.y * 64;
    int tid = threadIdx.y * 16 + threadIdx.x;
    for (int i = tid; i < 4096; i += 128) {
        int r = i >> 6, k = i & 63; int n = rowBase + r;
        sX[i] = (n < NATOM) ? g_x[n * 64 + k] : 0.f;
    }
    {
        const float2* Wg = g_W1p + L * KPA * PAS;
        for (int i = tid; i < KPA * 64; i += 128) {
            int kp = i >> 6, cc = i & 63;
            int kp2 = kp >> 1, half = kp & 1;
            sW[(kp2 * 64 + (cc & 3) * 16 + (cc >> 2)) * 2 + half] = Wg[kp * PAS + colBase + cc];
        }
    }
    __syncthreads();
    int x = threadIdx.x, rq = threadIdx.y * 8;
    int col0 = colBase + x * 4;
    unsigned long long acc[8][4];
#pragma unroll
    for (int j = 0; j < 4; j++) {
        unsigned long long b = (unsigned long long)__float_as_uint(g_b1[L * PAS + col0 + j]);
#pragma unroll
        for (int i = 0; i < 8; i++) acc[i][j] = b;
    }
#pragma unroll
    for (int kp2 = 0; kp2 < KPA2; kp2++) {
        ulonglong2 wv[4];
#pragma unroll
        for (int j = 0; j < 4; j++)
            wv[j] = *(const ulonglong2*)&sW[(kp2 * 64 + j * 16 + x) * 2];
#pragma unroll
        for (int i = 0; i < 8; i++) {
            ulonglong2 sv = *(const ulonglong2*)(sX + (rq + i) * 64 + 4 * kp2);
#pragma unroll
            for (int j = 0; j < 4; j++) {
                fma2(acc[i][j], sv.x, wv[j].x);
                fma2(acc[i][j], sv.y, wv[j].y);
            }
        }
    }
#pragma unroll
    for (int i = 0; i < 8; i++) {
        int n = rowBase + rq + i;
        if (n < NATOM) {
            float4 v;
            v.x = lohi(acc[i][0]); v.y = lohi(acc[i][1]);
            v.z = lohi(acc[i][2]); v.w = lohi(acc[i][3]);
            *(float4*)&g_pa[n * PAS + col0] = v;     // padding cols unread
        }
    }
}

// ---------------- Per-edge GEMM + gather epilogue: g_hpq ----------------
// 128 threads (16x, 8y), thread tile 8 rows x 4 cols, block tile 64x64.
// Multi-tile: each block loops 5 row-tiles; weight smem load amortized.
__global__ __launch_bounds__(128, 4) void k_edge(int L, const int* __restrict__ idx) {
    __shared__ __align__(16) float  sT[64 * 44];
    __shared__ __align__(16) float2 sW[KPE * 64];
    __shared__ int sJ[64];
    int colBase = blockIdx.y * 64;
    int tid = threadIdx.y * 16 + threadIdx.x;
    {
        const float2* Wg = g_We2p + L * KPE * WSE;
        for (int i = tid; i < KPE * 64; i += 128) {
            int kp = i >> 6, cc = i & 63;
            int kp2 = kp >> 1, half = kp & 1;
            sW[(kp2 * 64 + (cc & 3) * 16 + (cc >> 2)) * 2 + half] = Wg[kp * WSE + colBase + cc];
        }
    }
    int x = threadIdx.x, rq = threadIdx.y * 8;
    int col0 = colBase + x * 4;

    for (int t = 0; t < 5; t++) {
        int rowBase = (blockIdx.x * 5 + t) * 64;
        __syncthreads();   // t=0: sW ready; t>0: previous tile's sT consumers done
        if (tid < 64) sJ[tid] = idx[rowBase + tid];
        for (int i = tid; i < 64 * 44; i += 128) {
            int r = i / 44, k = i - r * 44;
            sT[i] = (k < 41) ? g_e[(rowBase + r) * 41 + k] : 0.f;
        }
        __syncthreads();

        unsigned long long acc[8][4];
#pragma unroll
        for (int i = 0; i < 8; i++)
#pragma unroll
            for (int j = 0; j < 4; j++) acc[i][j] = 0ull;
#pragma unroll
        for (int kp2 = 0; kp2 < KPE2; kp2++) {
            ulonglong2 wv[4];
#pragma unroll
            for (int j = 0; j < 4; j++)
                wv[j] = *(const ulonglong2*)&sW[(kp2 * 64 + j * 16 + x) * 2];
#pragma unroll
            for (int i = 0; i < 8; i++) {
                ulonglong2 sv = *(const ulonglong2*)(sT + (rq + i) * 44 + 4 * kp2);
#pragma unroll
                for (int j = 0; j < 4; j++) {
                    fma2(acc[i][j], sv.x, wv[j].x);
                    fma2(acc[i][j], sv.y, wv[j].y);
                }
            }
        }
        if (col0 < OCV) {      // cols 466,467 are write-safe padding
#pragma unroll
            for (int i = 0; i < 8; i++) {
                int nm = rowBase + rq + i;
                int n = nm / MNB;
                int jat = sJ[rq + i];
                float4 pj = *(const float4*)&g_pa[jat * PAS + col0];   // x_j part
                float4 v;
                v.x = lohi(acc[i][0]) + pj.x;
                v.y = lohi(acc[i][1]) + pj.y;
                v.z = lohi(acc[i][2]) + pj.z;
                v.w = lohi(acc[i][3]) + pj.w;
                if (col0 + 3 < 210) {                                  // x_i part + bias (XI0 aligned)
                    float4 pi = *(const float4*)&g_pa[n * PAS + XI0 + col0];
                    v.x += pi.x; v.y += pi.y; v.z += pi.z; v.w += pi.w;
                } else if (col0 < 210) {                               // straddle at 208 (scalar)
                    if (col0 + 0 < 210) v.x += g_pa[n * PAS + XI0 + col0 + 0];
                    if (col0 + 1 < 210) v.y += g_pa[n * PAS + XI0 + col0 + 1];
                    if (col0 + 2 < 210) v.z += g_pa[n * PAS + XI0 + col0 + 2];
                    if (col0 + 3 < 210) v.w += g_pa[n * PAS + XI0 + col0 + 3];
                }
                *(float4*)&g_hpq[nm * OCP + col0] = v;
            }
        }
    }
}

// ---------------- statsA: BN1 partials (blocks 0..299) + BN3 partials (300..399) ----------------
__global__ __launch_bounds__(256) void k_statsA() {
    int b = blockIdx.x, c = threadIdx.x;
    if (b < 300) {
        if (c >= 210) return;
        int r0 = b * 80;
        float s = 0.f, s2 = 0.f;
#pragma unroll 4
        for (int r = r0; r < r0 + 80; r++) {
            float v = g_hpq[r * OCP + c];
            s += v; s2 = fmaf(v, v, s2);
        }
        g_part[b * 512 + c] = s;
        g_part[b * 512 + 256 + c] = s2;
    } else {
        if (c >= 128) return;
        int n0 = (b - 300) * 20;
        float sm = 0.f, sv = 0.f;
        for (int n = n0; n < n0 + 20; n++) {
            float bb = g_pa[n * PAS + WA0 + c];
            float Sp = 0.f, Sp2 = 0.f, Sq = 0.f, Sq2 = 0.f;
#pragma unroll
            for (int m = 0; m < MNB; m++) {
                const float* row = g_hpq + (n * MNB + m) * OCP;
                float p = row[210 + c], q = row[338 + c];
                Sp += p; Sp2 = fmaf(p, p, Sp2); Sq += q; Sq2 = fmaf(q, q, Sq2);
            }
            sm += bb + (Sp + Sq) * (1.f / 12.f);
            sv += bb * bb + (Sp2 + Sq2) * (1.f / 12.f)
                + 2.f * bb * (Sp + Sq) * (1.f / 12.f)
                + 2.f * Sp * Sq * (1.f / 144.f);
        }
        g_part[b * 512 + c] = sm;
        g_part[b * 512 + 256 + c] = sv;
    }
}

// ---------------- statsB: finalize BN1 (c<210) and BN3 (c<128) scale/shift ----------------
__global__ __launch_bounds__(256) void k_statsB(int L, const float* __restrict__ g1, const float* __restrict__ b1,
                                                const float* __restrict__ ge, const float* __restrict__ be,
                                                const float* __restrict__ g3, const float* __restrict__ b3b) {
    int c = threadIdx.x;
    if (c < 210) {
        float S0 = 0.f, S1 = 0.f, T0 = 0.f, T1 = 0.f;
        for (int b = 0; b < 300; b += 2) {
            S0 += g_part[b * 512 + c];       S1 += g_part[(b + 1) * 512 + c];
            T0 += g_part[b * 512 + 256 + c]; T1 += g_part[(b + 1) * 512 + 256 + c];
        }
        float m = (S0 + S1) * (1.f / 24000.f);
        float v = (T0 + T1) * (1.f / 24000.f) - m * m; if (v < 0.f) v = 0.f;
        float gm, bt;
        if (c < 128) { gm = g1[L * 128 + c]; bt = b1[L * 128 + c]; }
        else         { gm = ge[L * 82 + c - 128]; bt = be[L * 82 + c - 128]; }
        float sc = gm * rsqrtf(v + 1e-5f);
        g_bn[c] = sc;
        g_bn[256 + c] = bt - m * sc;
    }
    if (c < 128) {
        float S0 = 0.f, S1 = 0.f, T0 = 0.f, T1 = 0.f;
        for (int b = 300; b < 400; b += 2) {
            S0 += g_part[b * 512 + c];       S1 += g_part[(b + 1) * 512 + c];
            T0 += g_part[b * 512 + 256 + c]; T1 += g_part[(b + 1) * 512 + 256 + c];
        }
        float m = (S0 + S1) * (1.f / 2000.f);
        float v = (T0 + T1) * (1.f / 2000.f) - m * m; if (v < 0.f) v = 0.f;
        float sc = g3[L * 128 + c] * rsqrtf(v + 1e-5f);
        g_bn[512 + c] = sc;
        g_bn[640 + c] = b3b[L * 128 + c] - m * sc;
    }
}

// ---------------- point: twobody (b<1000) | eupd (1000..8687) | threebody (8688..9687) ----------------
__global__ __launch_bounds__(128) void k_point() {
    int b = blockIdx.x, t = threadIdx.x;
    if (b < 1000) {
        int n = b * 2 + (t >> 6), c = t & 63;
        float sa = g_bn[c], ta = g_bn[256 + c];
        float sb = g_bn[64 + c], tb = g_bn[320 + c];
        const float* row = g_hpq + n * MNB * OCP;
        float acc = 0.f;
#pragma unroll
        for (int m = 0; m < MNB; m++) {
            float z1 = fmaf(sa, row[m * OCP + c], ta);
            float z2 = fmaf(sb, row[m * OCP + 64 + c], tb);
            acc += sigf(z1) * spf(z2);
        }
        g_total[n * AF + c] = acc;
    } else if (b < 8688) {
        int i = (b - 1000) * 128 + t;
        if (i >= NEL) return;
        int nm = i / BFD, cb = i - nm * BFD;
        float z1 = fmaf(g_bn[128 + cb], g_hpq[nm * OCP + 128 + cb], g_bn[384 + cb]);
        float z2 = fmaf(g_bn[169 + cb], g_hpq[nm * OCP + 169 + cb], g_bn[425 + cb]);
        g_e[i] += sigf(z1) * spf(z2);
    } else {
        // three-body with exp-factorization: sigmoid(ag+vg[l])*softplus(af+vf[l])
        //  = log(1 + e^{af}e^{vf[l]}) / (1 + e^{-ag}e^{-vg[l]})
        int n = (b - 8688) * 2 + (t >> 6), c = t & 63;
        float sg = g_bn[512 + c], tg = g_bn[640 + c];
        float sf = g_bn[576 + c], tf = g_bn[704 + c];
        float bg = fmaf(sg, g_pa[n * PAS + WA0 + c], tg);
        float bf = fmaf(sf, g_pa[n * PAS + WA0 + 64 + c], tf);
        float ug[12], uf[12], Evg[12], Evf[12];
#pragma unroll
        for (int m = 0; m < MNB; m++) {
            const float* row = g_hpq + (n * MNB + m) * OCP;
            ug[m] = sg * row[210 + c];
            uf[m] = sf * row[274 + c];
            Evg[m] = __expf(-sg * row[338 + c]);
            Evf[m] = __expf(sf * row[402 + c]);
        }
        float acc = 0.f;
#pragma unroll
        for (int m = 0; m < MNB; m++) {
            float Eag = __expf(-(bg + ug[m]));
            float Faf = __expf(bf + uf[m]);
#pragma unroll
            for (int l = 0; l < MNB; l++) {
                float den = fmaf(Eag, Evg[l], 1.f);
                float num = fmaf(Faf, Evf[l], 1.f);
                acc += __fdividef(__logf(num), den);
            }
        }
        g_t3[n * AF + c] = acc;
    }
}

// ---------------- BN2 partials ----------------
__global__ __launch_bounds__(64) void k_stats2_part() {
    int c = threadIdx.x;
    int r0 = blockIdx.x * 40;
    float s = 0.f, s2 = 0.f;
    for (int r = r0; r < r0 + 40; r++) {
        float v = g_total[r * AF + c] + g_t3[r * AF + c];
        s += v; s2 = fmaf(v, v, s2);
    }
    g_part[blockIdx.x * 512 + c] = s;
    g_part[blockIdx.x * 512 + 64 + c] = s2;
}

// ---------------- BN2 finalize (redundant per block) + x update ----------------
__global__ __launch_bounds__(1024) void k_xupd(int L, const float* __restrict__ g2,
                                               const float* __restrict__ b2) {
    __shared__ float s_sc[64], s_sh[64];
    int t = threadIdx.x;
    if (t < 64) {
        float S = 0.f, S2 = 0.f;
        for (int b = 0; b < 50; b++) { S += g_part[b * 512 + t]; S2 += g_part[b * 512 + 64 + t]; }
        float m = S * (1.f / 2000.f);
        float v = S2 * (1.f / 2000.f) - m * m; if (v < 0.f) v = 0.f;
        float sc = g2[L * 64 + t] * rsqrtf(v + 1e-5f);
        s_sc[t] = sc;
        s_sh[t] = b2[L * 64 + t] - m * sc;
    }
    __syncthreads();
    int i = blockIdx.x * 1024 + t;
    int c = i & 63;
    float tot = g_total[i] + g_t3[i];
    float z = g_x[i] + fmaf(s_sc[c], tot, s_sh[c]);
    g_x[i] = spf(z);
}

// ---------------- head: fc1 + softplus ----------------
__global__ __launch_bounds__(128) void k_fc1(const float* __restrict__ W, const float* __restrict__ b) {
    __shared__ float sx[16 * 64];
    int n0 = blockIdx.x * 16, h = threadIdx.x;
    for (int i = h; i < 1024; i += 128) sx[i] = spf(g_x[n0 * 64 + i]);
    __syncthreads();
    float acc[16]; float bb = b[h];
#pragma unroll
    for (int r = 0; r < 16; r++) acc[r] = bb;
    for (int k = 0; k < 64; k++) {
        float w = W[h * 64 + k];
#pragma unroll
        for (int r = 0; r < 16; r++) acc[r] = fmaf(sx[r * 64 + k], w, acc[r]);
    }
#pragma unroll
    for (int r = 0; r < 16; r++) g_y[(n0 + r) * 128 + h] = spf(acc[r]);
}

// ---------------- segment-mean pool + output dot ----------------
__global__ __launch_bounds__(128) void k_pool(const int* __restrict__ seg, const float* __restrict__ outW,
                                              const float* __restrict__ outb, float* __restrict__ out) {
    __shared__ int sseg[NATOM];
    __shared__ float red[128];
    int g = blockIdx.x, c = threadIdx.x;
    for (int i = c; i < NATOM; i += 128) sseg[i] = seg[i];
    __syncthreads();
    float sum = 0.f; int cnt = 0;
    for (int n = 0; n < NATOM; n++) {       // site_seg is sorted ascending
        int s = sseg[n];
        if (s > g) break;
        if (s == g) { sum += g_y[n * 128 + c]; cnt++; }
    }
    red[c] = sum * outW[c];
    __syncthreads();
    for (int s = 64; s > 0; s >>= 1) {
        if (c < s) red[c] += red[c + s];
        __syncthreads();
    }
    if (c == 0) out[g] = red[0] / fmaxf((float)cnt, 1.f) + outb[0];
}

// ---------------- launch ----------------
extern "C" void kernel_launch(void* const* d_in, const int* in_sizes, int n_in,
                              void* d_out, int out_size) {
    const float* atom = (const float*)d_in[0];
    const float* nbr  = (const float*)d_in[1];
    const int*   idx  = (const int*)d_in[2];
    const int*   seg  = (const int*)d_in[3];
    const float* embW = (const float*)d_in[4];
    const float* embb = (const float*)d_in[5];
    const float* fcW  = (const float*)d_in[6];
    const float* fcb  = (const float*)d_in[7];
    const float* bn1g = (const float*)d_in[8];
    const float* bn1b = (const float*)d_in[9];
    const float* bn2g = (const float*)d_in[10];
    const float* bn2b = (const float*)d_in[11];
    const float* eW   = (const float*)d_in[12];
    const float* eb   = (const float*)d_in[13];
    const float* bneg = (const float*)d_in[14];
    const float* bneb = (const float*)d_in[15];
    const float* W3   = (const float*)d_in[16];
    const float* b3   = (const float*)d_in[17];
    const float* bn3g = (const float*)d_in[18];
    const float* bn3b = (const float*)d_in[19];
    const float* fc1W = (const float*)d_in[20];
    const float* fc1b = (const float*)d_in[21];
    const float* outW = (const float*)d_in[22];
    const float* outb = (const float*)d_in[23];
    float* out = (float*)d_out;

    const int PACK_N = 3 * KPE * WSE + 3 * KPA * PAS + 3 * PAS + 92 * 64 + NEL;
    k_pack<<<(PACK_N + 255) / 256, 256>>>(fcW, eW, W3, fcb, eb, b3, embW, nbr);
    k_emb<<<NATOM / 16, 64>>>(atom, embb);

    for (int L = 0; L < 3; L++) {
        k_pa<<<dim3(32, 13), dim3(16, 8)>>>(L);
        k_edge<<<dim3(75, 8), dim3(16, 8)>>>(L, idx);
        k_statsA<<<400, 256>>>();
        k_statsB<<<1, 256>>>(L, bn1g, bn1b, bneg, bneb, bn3g, bn3b);
        k_point<<<9688, 128>>>();
        k_stats2_part<<<50, 64>>>();
        k_xupd<<<125, 1024>>>(L, bn2g, bn2b);
    }

    k_fc1<<<NATOM / 16, 128>>>(fc1W, fc1b);
    k_pool<<<NCR, 128>>>(seg, outW, outb, out);
}

// round 13
// speedup vs baseline: 1.0090x; 1.0090x over previous
#include <cuda_runtime.h>
#include <cuda_bf16.h>
#include <math.h>

// ---------------- Problem constants ----------------
#define NATOM 2000
#define MNB   12
#define NM    24000        // NATOM*MNB edges
#define AF    64
#define BFD   41
#define EP    44           // padded edge-feature stride (16B-multiple rows: 44*4=176)
#define PAS   832          // per-atom output stride (806 valid cols)
#define XI0   468          // aligned base of x_i section in g_pa
#define WA0   678          // base of Wa (3-body base) section in g_pa
#define OCV   466          // per-edge valid cols: 128 h | 82 he | 128 P | 128 Q
#define OCP   468          // padded row stride
#define WSE   512          // edge weight col stride
#define KPE   22           // edge K pairs (K=41 padded to 44)
#define KPE2  11
#define KPA   32           // atom K pairs (K=64)
#define KPA2  16
#define NCR   64
#define NEL   (NM * BFD)   // 984000 logical edge-feature elements

// ---------------- Device scratch ----------------
__device__ float  g_x[NATOM * AF];
__device__ __align__(16) float g_e[NM * EP];
__device__ float  g_pa[NATOM * PAS];
__device__ float  g_hpq[NM * OCP];
__device__ float  g_total[NATOM * AF];
__device__ float  g_t3[NATOM * AF];
__device__ float  g_y[NATOM * 128];
__device__ float2 g_W1p[3 * KPA * PAS];
__device__ float  g_b1[3 * PAS];
__device__ float2 g_We2p[3 * KPE * WSE];
__device__ float  g_We[92 * 64];
__device__ float  g_bn[1024];
__device__ float  g_part[400 * 512];

// ---------------- Math helpers ----------------
__device__ __forceinline__ float spf(float x) {           // softplus
    return fmaxf(x, 0.f) + __logf(1.f + __expf(-fabsf(x)));
}
__device__ __forceinline__ float sigf(float x) {          // sigmoid
    return __fdividef(1.f, 1.f + __expf(-x));
}
__device__ __forceinline__ void fma2(unsigned long long& d, unsigned long long a, unsigned long long b) {
    asm("fma.rn.f32x2 %0, %1, %2, %0;" : "+l"(d) : "l"(a), "l"(b));
}
__device__ __forceinline__ float lohi(unsigned long long a) {
    return __uint_as_float((unsigned)a) + __uint_as_float((unsigned)(a >> 32));
}
__device__ __forceinline__ void cpa16(unsigned s, const void* g) {
    asm volatile("cp.async.cg.shared.global [%0], [%1], 16;" :: "r"(s), "l"(g));
}

// ---------------- Weight value maps ----------------
// fcW (3,128,169): [0,64)=x_i  [64,128)=x_j  [128,169)=e
// eW  (3, 82,169): same split
// W3  (3,128,274): Wa[0,64) Wj[64,128) Wl[128,192) Wij[192,233) Wil[233,274)
__device__ __forceinline__ float wpe(const float* fcW, const float* eW, const float* W3,
                                     int L, int k, int c) {
    if (k >= 41 || c >= OCV) return 0.f;
    if (c < 128) return fcW[(L * 128 + c) * 169 + 128 + k];
    if (c < 210) return eW[(L * 82 + c - 128) * 169 + 128 + k];
    if (c < 338) return W3[(L * 128 + c - 210) * 274 + 192 + k];   // Wij
    return W3[(L * 128 + c - 338) * 274 + 233 + k];                // Wil
}
__device__ __forceinline__ float wpa(const float* fcW, const float* eW, const float* W3,
                                     int L, int k, int o) {
    if (o < 128) return fcW[(L * 128 + o) * 169 + 64 + k];          // h:  x_j
    if (o < 210) return eW[(L * 82 + o - 128) * 169 + 64 + k];      // he: x_j
    if (o < 338) return W3[(L * 128 + o - 210) * 274 + 64 + k];     // Wj
    if (o < 466) return W3[(L * 128 + o - 338) * 274 + 128 + k];    // Wl
    if (o < XI0) return 0.f;
    if (o < XI0 + 128) return fcW[(L * 128 + o - XI0) * 169 + k];   // h:  x_i
    if (o < XI0 + 210) return eW[(L * 82 + o - XI0 - 128) * 169 + k]; // he: x_i
    if (o < WA0)       return 0.f;
    if (o < WA0 + 128) return W3[(L * 128 + o - WA0) * 274 + k];    // Wa
    return 0.f;
}

__global__ void k_pack(const float* __restrict__ fcW, const float* __restrict__ eW,
                       const float* __restrict__ W3, const float* __restrict__ fcb,
                       const float* __restrict__ eb, const float* __restrict__ b3,
                       const float* __restrict__ embW, const float* __restrict__ nbr) {
    int i = blockIdx.x * 256 + threadIdx.x;
    const int R0 = 3 * KPE * WSE;
    if (i < R0) {
        int L = i / (KPE * WSE); int r = i % (KPE * WSE);
        int kp = r / WSE, c = r % WSE;
        g_We2p[i] = make_float2(wpe(fcW, eW, W3, L, 2 * kp, c),
                                wpe(fcW, eW, W3, L, 2 * kp + 1, c));
        return;
    }
    i -= R0;
    const int R1 = 3 * KPA * PAS;
    if (i < R1) {
        int L = i / (KPA * PAS); int r = i % (KPA * PAS);
        int kp = r / PAS, o = r % PAS;
        g_W1p[i] = make_float2(wpa(fcW, eW, W3, L, 2 * kp, o),
                               wpa(fcW, eW, W3, L, 2 * kp + 1, o));
        return;
    }
    i -= R1;
    const int R2 = 3 * PAS;
    if (i < R2) {
        int L = i / PAS, o = i % PAS;
        float v = 0.f;
        if (o >= XI0 && o < XI0 + 128)            v = fcb[L * 128 + o - XI0];
        else if (o >= XI0 + 128 && o < XI0 + 210) v = eb[L * 82 + o - XI0 - 128];
        else if (o >= WA0 && o < WA0 + 128)       v = b3[L * 128 + o - WA0];
        g_b1[i] = v;
        return;
    }
    i -= R2;
    if (i < 92 * 64) { int k = i / 64, o = i % 64; g_We[i] = embW[o * 92 + k]; return; }
    i -= 92 * 64;
    if (i < NM * EP) {
        int nm = i / EP, cb = i - nm * EP;
        g_e[i] = (cb < BFD) ? nbr[nm * BFD + cb] : 0.f;
    }
}

// ---------------- Embedding ----------------
__global__ __launch_bounds__(64) void k_emb(const float* __restrict__ af, const float* __restrict__ eb) {
    __shared__ float sa[16 * 92];
    int n0 = blockIdx.x * 16, t = threadIdx.x;
    for (int i = t; i < 16 * 92; i += 64) sa[i] = af[n0 * 92 + i];
    __syncthreads();
    float acc[16]; float b = eb[t];
#pragma unroll
    for (int r = 0; r < 16; r++) acc[r] = b;
    for (int k = 0; k < 92; k++) {
        float w = g_We[k * 64 + t];
#pragma unroll
        for (int r = 0; r < 16; r++) acc[r] = fmaf(sa[r * 92 + k], w, acc[r]);
    }
#pragma unroll
    for (int r = 0; r < 16; r++) g_x[(n0 + r) * AF + t] = acc[r];
}

// ---------------- Per-atom GEMM: g_pa = x @ W1p + b1 ----------------
__global__ __launch_bounds__(128, 4) void k_pa(int L) {
    __shared__ __align__(16) float  sX[64 * 64];
    __shared__ __align__(16) float2 sW[KPA * 64];
    int rowBase = blockIdx.x * 64, colBase = blockIdx.y * 64;
    int tid = threadIdx.y * 16 + threadIdx.x;
    for (int i = tid; i < 4096; i += 128) {
        int r = i >> 6, k = i & 63; int n = rowBase + r;
        sX[i] = (n < NATOM) ? g_x[n * 64 + k] : 0.f;
    }
    {
        const float2* Wg = g_W1p + L * KPA * PAS;
        for (int i = tid; i < KPA * 64; i += 128) {
            int kp = i >> 6, cc = i & 63;
            int kp2 = kp >> 1, half = kp & 1;
            sW[(kp2 * 64 + (cc & 3) * 16 + (cc >> 2)) * 2 + half] = Wg[kp * PAS + colBase + cc];
        }
    }
    __syncthreads();
    int x = threadIdx.x, rq = threadIdx.y * 8;
    int col0 = colBase + x * 4;
    unsigned long long acc[8][4];
#pragma unroll
    for (int j = 0; j < 4; j++) {
        unsigned long long b = (unsigned long long)__float_as_uint(g_b1[L * PAS + col0 + j]);
#pragma unroll
        for (int i = 0; i < 8; i++) acc[i][j] = b;
    }
#pragma unroll
    for (int kp2 = 0; kp2 < KPA2; kp2++) {
        ulonglong2 wv[4];
#pragma unroll
        for (int j = 0; j < 4; j++)
            wv[j] = *(const ulonglong2*)&sW[(kp2 * 64 + j * 16 + x) * 2];
#pragma unroll
        for (int i = 0; i < 8; i++) {
            ulonglong2 sv = *(const ulonglong2*)(sX + (rq + i) * 64 + 4 * kp2);
#pragma unroll
            for (int j = 0; j < 4; j++) {
                fma2(acc[i][j], sv.x, wv[j].x);
                fma2(acc[i][j], sv.y, wv[j].y);
            }
        }
    }
#pragma unroll
    for (int i = 0; i < 8; i++) {
        int n = rowBase + rq + i;
        if (n < NATOM) {
            float4 v;
            v.x = lohi(acc[i][0]); v.y = lohi(acc[i][1]);
            v.z = lohi(acc[i][2]); v.w = lohi(acc[i][3]);
            *(float4*)&g_pa[n * PAS + col0] = v;
        }
    }
}

// ---------------- Per-edge GEMM + gather epilogue: g_hpq ----------------
// cp.async double-buffered tile pipeline: 5 row-tiles/block, fill hidden
// behind the previous tile's mainloop + epilogue.
__global__ __launch_bounds__(128, 4) void k_edge(int L, const int* __restrict__ idx) {
    __shared__ __align__(16) float  sT[2][64 * EP];
    __shared__ __align__(16) int    sJ[2][64];
    __shared__ __align__(16) float2 sW[KPE * 64];
    int colBase = blockIdx.y * 64;
    int tid = threadIdx.y * 16 + threadIdx.x;
    {
        const float2* Wg = g_We2p + L * KPE * WSE;
        for (int i = tid; i < KPE * 64; i += 128) {
            int kp = i >> 6, cc = i & 63;
            int kp2 = kp >> 1, half = kp & 1;
            sW[(kp2 * 64 + (cc & 3) * 16 + (cc >> 2)) * 2 + half] = Wg[kp * WSE + colBase + cc];
        }
    }
    int x = threadIdx.x, rq = threadIdx.y * 8;
    int col0 = colBase + x * 4;

    // prefetch tile 0 into buffer 0
    {
        int rowBase = blockIdx.x * 5 * 64;
        unsigned sj = (unsigned)__cvta_generic_to_shared(&sJ[0][0]);
        unsigned st = (unsigned)__cvta_generic_to_shared(&sT[0][0]);
        if (tid < 16) cpa16(sj + tid * 16, idx + rowBase + tid * 4);
        for (int i = tid; i < 704; i += 128)
            cpa16(st + i * 16, g_e + rowBase * EP + i * 4);
    }
    asm volatile("cp.async.commit_group;" ::: "memory");

    for (int t = 0; t < 5; t++) {
        int cur = t & 1;
        if (t < 4) {
            int rb = (blockIdx.x * 5 + t + 1) * 64;
            unsigned sj = (unsigned)__cvta_generic_to_shared(&sJ[1 - cur][0]);
            unsigned st = (unsigned)__cvta_generic_to_shared(&sT[1 - cur][0]);
            if (tid < 16) cpa16(sj + tid * 16, idx + rb + tid * 4);
            for (int i = tid; i < 704; i += 128)
                cpa16(st + i * 16, g_e + rb * EP + i * 4);
            asm volatile("cp.async.commit_group;" ::: "memory");
            asm volatile("cp.async.wait_group 1;" ::: "memory");
        } else {
            asm volatile("cp.async.wait_group 0;" ::: "memory");
        }
        __syncthreads();   // buffer cur complete for all threads

        int rowBase = (blockIdx.x * 5 + t) * 64;
        const float* sTc = sT[cur];
        unsigned long long acc[8][4];
#pragma unroll
        for (int i = 0; i < 8; i++)
#pragma unroll
            for (int j = 0; j < 4; j++) acc[i][j] = 0ull;
#pragma unroll
        for (int kp2 = 0; kp2 < KPE2; kp2++) {
            ulonglong2 wv[4];
#pragma unroll
            for (int j = 0; j < 4; j++)
                wv[j] = *(const ulonglong2*)&sW[(kp2 * 64 + j * 16 + x) * 2];
#pragma unroll
            for (int i = 0; i < 8; i++) {
                ulonglong2 sv = *(const ulonglong2*)(sTc + (rq + i) * EP + 4 * kp2);
#pragma unroll
                for (int j = 0; j < 4; j++) {
                    fma2(acc[i][j], sv.x, wv[j].x);
                    fma2(acc[i][j], sv.y, wv[j].y);
                }
            }
        }
        if (col0 < OCV) {      // cols 466,467 are write-safe padding
#pragma unroll
            for (int i = 0; i < 8; i++) {
                int nm = rowBase + rq + i;
                int n = nm / MNB;
                int jat = sJ[cur][rq + i];
                float4 pj = *(const float4*)&g_pa[jat * PAS + col0];   // x_j part
                float4 v;
                v.x = lohi(acc[i][0]) + pj.x;
                v.y = lohi(acc[i][1]) + pj.y;
                v.z = lohi(acc[i][2]) + pj.z;
                v.w = lohi(acc[i][3]) + pj.w;
                if (col0 + 3 < 210) {                                  // x_i part + bias
                    float4 pi = *(const float4*)&g_pa[n * PAS + XI0 + col0];
                    v.x += pi.x; v.y += pi.y; v.z += pi.z; v.w += pi.w;
                } else if (col0 < 210) {                               // straddle at 208
                    if (col0 + 0 < 210) v.x += g_pa[n * PAS + XI0 + col0 + 0];
                    if (col0 + 1 < 210) v.y += g_pa[n * PAS + XI0 + col0 + 1];
                    if (col0 + 2 < 210) v.z += g_pa[n * PAS + XI0 + col0 + 2];
                    if (col0 + 3 < 210) v.w += g_pa[n * PAS + XI0 + col0 + 3];
                }
                *(float4*)&g_hpq[nm * OCP + col0] = v;
            }
        }
        __syncthreads();   // protect buffer cur from next iteration's prefetch
    }
}

// ---------------- statsA: BN1 partials (blocks 0..299) + BN3 partials (300..399) ----------------
__global__ __launch_bounds__(256) void k_statsA() {
    int b = blockIdx.x, c = threadIdx.x;
    if (b < 300) {
        if (c >= 210) return;
        int r0 = b * 80;
        float s = 0.f, s2 = 0.f;
#pragma unroll 4
        for (int r = r0; r < r0 + 80; r++) {
            float v = g_hpq[r * OCP + c];
            s += v; s2 = fmaf(v, v, s2);
        }
        g_part[b * 512 + c] = s;
        g_part[b * 512 + 256 + c] = s2;
    } else {
        if (c >= 128) return;
        int n0 = (b - 300) * 20;
        float sm = 0.f, sv = 0.f;
        for (int n = n0; n < n0 + 20; n++) {
            float bb = g_pa[n * PAS + WA0 + c];
            float Sp = 0.f, Sp2 = 0.f, Sq = 0.f, Sq2 = 0.f;
#pragma unroll
            for (int m = 0; m < MNB; m++) {
                const float* row = g_hpq + (n * MNB + m) * OCP;
                float p = row[210 + c], q = row[338 + c];
                Sp += p; Sp2 = fmaf(p, p, Sp2); Sq += q; Sq2 = fmaf(q, q, Sq2);
            }
            sm += bb + (Sp + Sq) * (1.f / 12.f);
            sv += bb * bb + (Sp2 + Sq2) * (1.f / 12.f)
                + 2.f * bb * (Sp + Sq) * (1.f / 12.f)
                + 2.f * Sp * Sq * (1.f / 144.f);
        }
        g_part[b * 512 + c] = sm;
        g_part[b * 512 + 256 + c] = sv;
    }
}

// ---------------- statsB: finalize BN1 (c<210) and BN3 (c<128) scale/shift ----------------
__global__ __launch_bounds__(256) void k_statsB(int L, const float* __restrict__ g1, const float* __restrict__ b1,
                                                const float* __restrict__ ge, const float* __restrict__ be,
                                                const float* __restrict__ g3, const float* __restrict__ b3b) {
    int c = threadIdx.x;
    if (c < 210) {
        float S0 = 0.f, S1 = 0.f, T0 = 0.f, T1 = 0.f;
        for (int b = 0; b < 300; b += 2) {
            S0 += g_part[b * 512 + c];       S1 += g_part[(b + 1) * 512 + c];
            T0 += g_part[b * 512 + 256 + c]; T1 += g_part[(b + 1) * 512 + 256 + c];
        }
        float m = (S0 + S1) * (1.f / 24000.f);
        float v = (T0 + T1) * (1.f / 24000.f) - m * m; if (v < 0.f) v = 0.f;
        float gm, bt;
        if (c < 128) { gm = g1[L * 128 + c]; bt = b1[L * 128 + c]; }
        else         { gm = ge[L * 82 + c - 128]; bt = be[L * 82 + c - 128]; }
        float sc = gm * rsqrtf(v + 1e-5f);
        g_bn[c] = sc;
        g_bn[256 + c] = bt - m * sc;
    }
    if (c < 128) {
        float S0 = 0.f, S1 = 0.f, T0 = 0.f, T1 = 0.f;
        for (int b = 300; b < 400; b += 2) {
            S0 += g_part[b * 512 + c];       S1 += g_part[(b + 1) * 512 + c];
            T0 += g_part[b * 512 + 256 + c]; T1 += g_part[(b + 1) * 512 + 256 + c];
        }
        float m = (S0 + S1) * (1.f / 2000.f);
        float v = (T0 + T1) * (1.f / 2000.f) - m * m; if (v < 0.f) v = 0.f;
        float sc = g3[L * 128 + c] * rsqrtf(v + 1e-5f);
        g_bn[512 + c] = sc;
        g_bn[640 + c] = b3b[L * 128 + c] - m * sc;
    }
}

// ---------------- point: twobody (b<1000) | eupd (1000..8687) | threebody (8688..9687) ----------------
__global__ __launch_bounds__(128) void k_point() {
    int b = blockIdx.x, t = threadIdx.x;
    if (b < 1000) {
        int n = b * 2 + (t >> 6), c = t & 63;
        float sa = g_bn[c], ta = g_bn[256 + c];
        float sb = g_bn[64 + c], tb = g_bn[320 + c];
        const float* row = g_hpq + n * MNB * OCP;
        float acc = 0.f;
#pragma unroll
        for (int m = 0; m < MNB; m++) {
            float z1 = fmaf(sa, row[m * OCP + c], ta);
            float z2 = fmaf(sb, row[m * OCP + 64 + c], tb);
            acc += sigf(z1) * spf(z2);
        }
        g_total[n * AF + c] = acc;
    } else if (b < 8688) {
        int i = (b - 1000) * 128 + t;
        if (i >= NEL) return;
        int nm = i / BFD, cb = i - nm * BFD;
        float z1 = fmaf(g_bn[128 + cb], g_hpq[nm * OCP + 128 + cb], g_bn[384 + cb]);
        float z2 = fmaf(g_bn[169 + cb], g_hpq[nm * OCP + 169 + cb], g_bn[425 + cb]);
        g_e[nm * EP + cb] += sigf(z1) * spf(z2);
    } else {
        // three-body with exp-factorization
        int n = (b - 8688) * 2 + (t >> 6), c = t & 63;
        float sg = g_bn[512 + c], tg = g_bn[640 + c];
        float sf = g_bn[576 + c], tf = g_bn[704 + c];
        float bg = fmaf(sg, g_pa[n * PAS + WA0 + c], tg);
        float bf = fmaf(sf, g_pa[n * PAS + WA0 + 64 + c], tf);
        float ug[12], uf[12], Evg[12], Evf[12];
#pragma unroll
        for (int m = 0; m < MNB; m++) {
            const float* row = g_hpq + (n * MNB + m) * OCP;
            ug[m] = sg * row[210 + c];
            uf[m] = sf * row[274 + c];
            Evg[m] = __expf(-sg * row[338 + c]);
            Evf[m] = __expf(sf * row[402 + c]);
        }
        float acc = 0.f;
#pragma unroll
        for (int m = 0; m < MNB; m++) {
            float Eag = __expf(-(bg + ug[m]));
            float Faf = __expf(bf + uf[m]);
#pragma unroll
            for (int l = 0; l < MNB; l++) {
                float den = fmaf(Eag, Evg[l], 1.f);
                float num = fmaf(Faf, Evf[l], 1.f);
                acc += __fdividef(__logf(num), den);
            }
        }
        g_t3[n * AF + c] = acc;
    }
}

// ---------------- BN2 partials ----------------
__global__ __launch_bounds__(64) void k_stats2_part() {
    int c = threadIdx.x;
    int r0 = blockIdx.x * 40;
    float s = 0.f, s2 = 0.f;
    for (int r = r0; r < r0 + 40; r++) {
        float v = g_total[r * AF + c] + g_t3[r * AF + c];
        s += v; s2 = fmaf(v, v, s2);
    }
    g_part[blockIdx.x * 512 + c] = s;
    g_part[blockIdx.x * 512 + 64 + c] = s2;
}

// ---------------- BN2 finalize (redundant per block) + x update ----------------
__global__ __launch_bounds__(1024) void k_xupd(int L, const float* __restrict__ g2,
                                               const float* __restrict__ b2) {
    __shared__ float s_sc[64], s_sh[64];
    int t = threadIdx.x;
    if (t < 64) {
        float S = 0.f, S2 = 0.f;
        for (int b = 0; b < 50; b++) { S += g_part[b * 512 + t]; S2 += g_part[b * 512 + 64 + t]; }
        float m = S * (1.f / 2000.f);
        float v = S2 * (1.f / 2000.f) - m * m; if (v < 0.f) v = 0.f;
        float sc = g2[L * 64 + t] * rsqrtf(v + 1e-5f);
        s_sc[t] = sc;
        s_sh[t] = b2[L * 64 + t] - m * sc;
    }
    __syncthreads();
    int i = blockIdx.x * 1024 + t;
    int c = i & 63;
    float tot = g_total[i] + g_t3[i];
    float z = g_x[i] + fmaf(s_sc[c], tot, s_sh[c]);
    g_x[i] = spf(z);
}

// ---------------- head: fc1 + softplus ----------------
__global__ __launch_bounds__(128) void k_fc1(const float* __restrict__ W, const float* __restrict__ b) {
    __shared__ float sx[16 * 64];
    int n0 = blockIdx.x * 16, h = threadIdx.x;
    for (int i = h; i < 1024; i += 128) sx[i] = spf(g_x[n0 * 64 + i]);
    __syncthreads();
    float acc[16]; float bb = b[h];
#pragma unroll
    for (int r = 0; r < 16; r++) acc[r] = bb;
    for (int k = 0; k < 64; k++) {
        float w = W[h * 64 + k];
#pragma unroll
        for (int r = 0; r < 16; r++) acc[r] = fmaf(sx[r * 64 + k], w, acc[r]);
    }
#pragma unroll
    for (int r = 0; r < 16; r++) g_y[(n0 + r) * 128 + h] = spf(acc[r]);
}

// ---------------- segment-mean pool + output dot ----------------
__global__ __launch_bounds__(128) void k_pool(const int* __restrict__ seg, const float* __restrict__ outW,
                                              const float* __restrict__ outb, float* __restrict__ out) {
    __shared__ int sseg[NATOM];
    __shared__ float red[128];
    int g = blockIdx.x, c = threadIdx.x;
    for (int i = c; i < NATOM; i += 128) sseg[i] = seg[i];
    __syncthreads();
    float sum = 0.f; int cnt = 0;
    for (int n = 0; n < NATOM; n++) {       // site_seg is sorted ascending
        int s = sseg[n];
        if (s > g) break;
        if (s == g) { sum += g_y[n * 128 + c]; cnt++; }
    }
    red[c] = sum * outW[c];
    __syncthreads();
    for (int s = 64; s > 0; s >>= 1) {
        if (c < s) red[c] += red[c + s];
        __syncthreads();
    }
    if (c == 0) out[g] = red[0] / fmaxf((float)cnt, 1.f) + outb[0];
}

// ---------------- launch ----------------
extern "C" void kernel_launch(void* const* d_in, const int* in_sizes, int n_in,
                              void* d_out, int out_size) {
    const float* atom = (const float*)d_in[0];
    const float* nbr  = (const float*)d_in[1];
    const int*   idx  = (const int*)d_in[2];
    const int*   seg  = (const int*)d_in[3];
    const float* embW = (const float*)d_in[4];
    const float* embb = (const float*)d_in[5];
    const float* fcW  = (const float*)d_in[6];
    const float* fcb  = (const float*)d_in[7];
    const float* bn1g = (const float*)d_in[8];
    const float* bn1b = (const float*)d_in[9];
    const float* bn2g = (const float*)d_in[10];
    const float* bn2b = (const float*)d_in[11];
    const float* eW   = (const float*)d_in[12];
    const float* eb   = (const float*)d_in[13];
    const float* bneg = (const float*)d_in[14];
    const float* bneb = (const float*)d_in[15];
    const float* W3   = (const float*)d_in[16];
    const float* b3   = (const float*)d_in[17];
    const float* bn3g = (const float*)d_in[18];
    const float* bn3b = (const float*)d_in[19];
    const float* fc1W = (const float*)d_in[20];
    const float* fc1b = (const float*)d_in[21];
    const float* outW = (const float*)d_in[22];
    const float* outb = (const float*)d_in[23];
    float* out = (float*)d_out;

    const int PACK_N = 3 * KPE * WSE + 3 * KPA * PAS + 3 * PAS + 92 * 64 + NM * EP;
    k_pack<<<(PACK_N + 255) / 256, 256>>>(fcW, eW, W3, fcb, eb, b3, embW, nbr);
    k_emb<<<NATOM / 16, 64>>>(atom, embb);

    for (int L = 0; L < 3; L++) {
        k_pa<<<dim3(32, 13), dim3(16, 8)>>>(L);
        k_edge<<<dim3(75, 8), dim3(16, 8)>>>(L, idx);
        k_statsA<<<400, 256>>>();
        k_statsB<<<1, 256>>>(L, bn1g, bn1b, bneg, bneb, bn3g, bn3b);
        k_point<<<9688, 128>>>();
        k_stats2_part<<<50, 64>>>();
        k_xupd<<<125, 1024>>>(L, bn2g, bn2b);
    }

    k_fc1<<<NATOM / 16, 128>>>(fc1W, fc1b);
    k_pool<<<NCR, 128>>>(seg, outW, outb, out);
}

// round 14
// speedup vs baseline: 1.0557x; 1.0463x over previous
#include <cuda_runtime.h>
#include <cuda_bf16.h>
#include <math.h>

// ---------------- Problem constants ----------------
#define NATOM 2000
#define MNB   12
#define NM    24000        // NATOM*MNB edges
#define AF    64
#define BFD   41
#define EP    44           // padded edge-feature stride (44*4=176 B, 16B multiple)
#define PAS   832          // per-atom output stride (806 valid cols)
#define XI0   468          // aligned base of x_i section in g_pa
#define WA0   678          // base of Wa (3-body base) section in g_pa
#define OCV   466          // per-edge valid cols: 128 h | 82 he | 128 P | 128 Q
#define OCP   468          // padded row stride
#define WSE   512          // edge weight col stride
#define KPE   22
#define KPE2  11
#define KPA   32
#define KPA2  16
#define NCR   64
#define NEL   (NM * BFD)

// ---------------- Device scratch ----------------
__device__ float  g_x[NATOM * AF];
__device__ __align__(16) float g_e[NM * EP];
__device__ float  g_pa[NATOM * PAS];
__device__ float  g_hpq[NM * OCP];
__device__ float  g_total[NATOM * AF];
__device__ float  g_y[NATOM * 128];
__device__ float2 g_W1p[3 * KPA * PAS];
__device__ float  g_b1[3 * PAS];
__device__ float2 g_We2p[3 * KPE * WSE];
__device__ float  g_We[92 * 64];
__device__ float  g_bn[1024];
__device__ float  g_part[400 * 512];
__device__ int    g_cnt;           // statsA completion counter (self-resetting)

// ---------------- Math helpers ----------------
__device__ __forceinline__ float spf(float x) {
    return fmaxf(x, 0.f) + __logf(1.f + __expf(-fabsf(x)));
}
__device__ __forceinline__ float sigf(float x) {
    return __fdividef(1.f, 1.f + __expf(-x));
}
__device__ __forceinline__ void fma2(unsigned long long& d, unsigned long long a, unsigned long long b) {
    asm("fma.rn.f32x2 %0, %1, %2, %0;" : "+l"(d) : "l"(a), "l"(b));
}
__device__ __forceinline__ float lohi(unsigned long long a) {
    return __uint_as_float((unsigned)a) + __uint_as_float((unsigned)(a >> 32));
}
__device__ __forceinline__ void cpa16(unsigned s, const void* g) {
    asm volatile("cp.async.cg.shared.global [%0], [%1], 16;" :: "r"(s), "l"(g));
}

// ---------------- Weight value maps ----------------
// fcW (3,128,169): [0,64)=x_i  [64,128)=x_j  [128,169)=e
// eW  (3, 82,169): same split
// W3  (3,128,274): Wa[0,64) Wj[64,128) Wl[128,192) Wij[192,233) Wil[233,274)
__device__ __forceinline__ float wpe(const float* fcW, const float* eW, const float* W3,
                                     int L, int k, int c) {
    if (k >= 41 || c >= OCV) return 0.f;
    if (c < 128) return fcW[(L * 128 + c) * 169 + 128 + k];
    if (c < 210) return eW[(L * 82 + c - 128) * 169 + 128 + k];
    if (c < 338) return W3[(L * 128 + c - 210) * 274 + 192 + k];
    return W3[(L * 128 + c - 338) * 274 + 233 + k];
}
__device__ __forceinline__ float wpa(const float* fcW, const float* eW, const float* W3,
                                     int L, int k, int o) {
    if (o < 128) return fcW[(L * 128 + o) * 169 + 64 + k];
    if (o < 210) return eW[(L * 82 + o - 128) * 169 + 64 + k];
    if (o < 338) return W3[(L * 128 + o - 210) * 274 + 64 + k];
    if (o < 466) return W3[(L * 128 + o - 338) * 274 + 128 + k];
    if (o < XI0) return 0.f;
    if (o < XI0 + 128) return fcW[(L * 128 + o - XI0) * 169 + k];
    if (o < XI0 + 210) return eW[(L * 82 + o - XI0 - 128) * 169 + k];
    if (o < WA0)       return 0.f;
    if (o < WA0 + 128) return W3[(L * 128 + o - WA0) * 274 + k];
    return 0.f;
}

__global__ void k_pack(const float* __restrict__ fcW, const float* __restrict__ eW,
                       const float* __restrict__ W3, const float* __restrict__ fcb,
                       const float* __restrict__ eb, const float* __restrict__ b3,
                       const float* __restrict__ embW, const float* __restrict__ nbr) {
    int i = blockIdx.x * 256 + threadIdx.x;
    const int R0 = 3 * KPE * WSE;
    if (i < R0) {
        int L = i / (KPE * WSE); int r = i % (KPE * WSE);
        int kp = r / WSE, c = r % WSE;
        g_We2p[i] = make_float2(wpe(fcW, eW, W3, L, 2 * kp, c),
                                wpe(fcW, eW, W3, L, 2 * kp + 1, c));
        return;
    }
    i -= R0;
    const int R1 = 3 * KPA * PAS;
    if (i < R1) {
        int L = i / (KPA * PAS); int r = i % (KPA * PAS);
        int kp = r / PAS, o = r % PAS;
        g_W1p[i] = make_float2(wpa(fcW, eW, W3, L, 2 * kp, o),
                               wpa(fcW, eW, W3, L, 2 * kp + 1, o));
        return;
    }
    i -= R1;
    const int R2 = 3 * PAS;
    if (i < R2) {
        int L = i / PAS, o = i % PAS;
        float v = 0.f;
        if (o >= XI0 && o < XI0 + 128)            v = fcb[L * 128 + o - XI0];
        else if (o >= XI0 + 128 && o < XI0 + 210) v = eb[L * 82 + o - XI0 - 128];
        else if (o >= WA0 && o < WA0 + 128)       v = b3[L * 128 + o - WA0];
        g_b1[i] = v;
        return;
    }
    i -= R2;
    if (i < 92 * 64) { int k = i / 64, o = i % 64; g_We[i] = embW[o * 92 + k]; return; }
    i -= 92 * 64;
    if (i < NM * EP) {
        int nm = i / EP, cb = i - nm * EP;
        g_e[i] = (cb < BFD) ? nbr[nm * BFD + cb] : 0.f;
    }
}

// ---------------- Embedding ----------------
__global__ __launch_bounds__(64) void k_emb(const float* __restrict__ af, const float* __restrict__ eb) {
    __shared__ float sa[16 * 92];
    int n0 = blockIdx.x * 16, t = threadIdx.x;
    for (int i = t; i < 16 * 92; i += 64) sa[i] = af[n0 * 92 + i];
    __syncthreads();
    float acc[16]; float b = eb[t];
#pragma unroll
    for (int r = 0; r < 16; r++) acc[r] = b;
    for (int k = 0; k < 92; k++) {
        float w = g_We[k * 64 + t];
#pragma unroll
        for (int r = 0; r < 16; r++) acc[r] = fmaf(sa[r * 92 + k], w, acc[r]);
    }
#pragma unroll
    for (int r = 0; r < 16; r++) g_x[(n0 + r) * AF + t] = acc[r];
}

// ---------------- Per-atom GEMM ----------------
__global__ __launch_bounds__(128, 4) void k_pa(int L) {
    __shared__ __align__(16) float  sX[64 * 64];
    __shared__ __align__(16) float2 sW[KPA * 64];
    int rowBase = blockIdx.x * 64, colBase = blockIdx.y * 64;
    int tid = threadIdx.y * 16 + threadIdx.x;
    for (int i = tid; i < 4096; i += 128) {
        int r = i >> 6, k = i & 63; int n = rowBase + r;
        sX[i] = (n < NATOM) ? g_x[n * 64 + k] : 0.f;
    }
    {
        const float2* Wg = g_W1p + L * KPA * PAS;
        for (int i = tid; i < KPA * 64; i += 128) {
            int kp = i >> 6, cc = i & 63;
            int kp2 = kp >> 1, half = kp & 1;
            sW[(kp2 * 64 + (cc & 3) * 16 + (cc >> 2)) * 2 + half] = Wg[kp * PAS + colBase + cc];
        }
    }
    __syncthreads();
    int x = threadIdx.x, rq = threadIdx.y * 8;
    int col0 = colBase + x * 4;
    unsigned long long acc[8][4];
#pragma unroll
    for (int j = 0; j < 4; j++) {
        unsigned long long b = (unsigned long long)__float_as_uint(g_b1[L * PAS + col0 + j]);
#pragma unroll
        for (int i = 0; i < 8; i++) acc[i][j] = b;
    }
#pragma unroll
    for (int kp2 = 0; kp2 < KPA2; kp2++) {
        ulonglong2 wv[4];
#pragma unroll
        for (int j = 0; j < 4; j++)
            wv[j] = *(const ulonglong2*)&sW[(kp2 * 64 + j * 16 + x) * 2];
#pragma unroll
        for (int i = 0; i < 8; i++) {
            ulonglong2 sv = *(const ulonglong2*)(sX + (rq + i) * 64 + 4 * kp2);
#pragma unroll
            for (int j = 0; j < 4; j++) {
                fma2(acc[i][j], sv.x, wv[j].x);
                fma2(acc[i][j], sv.y, wv[j].y);
            }
        }
    }
#pragma unroll
    for (int i = 0; i < 8; i++) {
        int n = rowBase + rq + i;
        if (n < NATOM) {
            float4 v;
            v.x = lohi(acc[i][0]); v.y = lohi(acc[i][1]);
            v.z = lohi(acc[i][2]); v.w = lohi(acc[i][3]);
            *(float4*)&g_pa[n * PAS + col0] = v;
        }
    }
}

// ---------------- Per-edge GEMM + gather epilogue (cp.async double-buffered) ----------------
__global__ __launch_bounds__(128, 4) void k_edge(int L, const int* __restrict__ idx) {
    __shared__ __align__(16) float  sT[2][64 * EP];
    __shared__ __align__(16) int    sJ[2][64];
    __shared__ __align__(16) float2 sW[KPE * 64];
    int colBase = blockIdx.y * 64;
    int tid = threadIdx.y * 16 + threadIdx.x;
    {
        const float2* Wg = g_We2p + L * KPE * WSE;
        for (int i = tid; i < KPE * 64; i += 128) {
            int kp = i >> 6, cc = i & 63;
            int kp2 = kp >> 1, half = kp & 1;
            sW[(kp2 * 64 + (cc & 3) * 16 + (cc >> 2)) * 2 + half] = Wg[kp * WSE + colBase + cc];
        }
    }
    int x = threadIdx.x, rq = threadIdx.y * 8;
    int col0 = colBase + x * 4;

    {
        int rowBase = blockIdx.x * 5 * 64;
        unsigned sj = (unsigned)__cvta_generic_to_shared(&sJ[0][0]);
        unsigned st = (unsigned)__cvta_generic_to_shared(&sT[0][0]);
        if (tid < 16) cpa16(sj + tid * 16, idx + rowBase + tid * 4);
        for (int i = tid; i < 704; i += 128)
            cpa16(st + i * 16, g_e + rowBase * EP + i * 4);
    }
    asm volatile("cp.async.commit_group;" ::: "memory");

    for (int t = 0; t < 5; t++) {
        int cur = t & 1;
        if (t < 4) {
            int rb = (blockIdx.x * 5 + t + 1) * 64;
            unsigned sj = (unsigned)__cvta_generic_to_shared(&sJ[1 - cur][0]);
            unsigned st = (unsigned)__cvta_generic_to_shared(&sT[1 - cur][0]);
            if (tid < 16) cpa16(sj + tid * 16, idx + rb + tid * 4);
            for (int i = tid; i < 704; i += 128)
                cpa16(st + i * 16, g_e + rb * EP + i * 4);
            asm volatile("cp.async.commit_group;" ::: "memory");
            asm volatile("cp.async.wait_group 1;" ::: "memory");
        } else {
            asm volatile("cp.async.wait_group 0;" ::: "memory");
        }
        __syncthreads();

        int rowBase = (blockIdx.x * 5 + t) * 64;
        const float* sTc = sT[cur];
        unsigned long long acc[8][4];
#pragma unroll
        for (int i = 0; i < 8; i++)
#pragma unroll
            for (int j = 0; j < 4; j++) acc[i][j] = 0ull;
#pragma unroll
        for (int kp2 = 0; kp2 < KPE2; kp2++) {
            ulonglong2 wv[4];
#pragma unroll
            for (int j = 0; j < 4; j++)
                wv[j] = *(const ulonglong2*)&sW[(kp2 * 64 + j * 16 + x) * 2];
#pragma unroll
            for (int i = 0; i < 8; i++) {
                ulonglong2 sv = *(const ulonglong2*)(sTc + (rq + i) * EP + 4 * kp2);
#pragma unroll
                for (int j = 0; j < 4; j++) {
                    fma2(acc[i][j], sv.x, wv[j].x);
                    fma2(acc[i][j], sv.y, wv[j].y);
                }
            }
        }
        if (col0 < OCV) {
#pragma unroll
            for (int i = 0; i < 8; i++) {
                int nm = rowBase + rq + i;
                int n = nm / MNB;
                int jat = sJ[cur][rq + i];
                float4 pj = *(const float4*)&g_pa[jat * PAS + col0];
                float4 v;
                v.x = lohi(acc[i][0]) + pj.x;
                v.y = lohi(acc[i][1]) + pj.y;
                v.z = lohi(acc[i][2]) + pj.z;
                v.w = lohi(acc[i][3]) + pj.w;
                if (col0 + 3 < 210) {
                    float4 pi = *(const float4*)&g_pa[n * PAS + XI0 + col0];
                    v.x += pi.x; v.y += pi.y; v.z += pi.z; v.w += pi.w;
                } else if (col0 < 210) {
                    if (col0 + 0 < 210) v.x += g_pa[n * PAS + XI0 + col0 + 0];
                    if (col0 + 1 < 210) v.y += g_pa[n * PAS + XI0 + col0 + 1];
                    if (col0 + 2 < 210) v.z += g_pa[n * PAS + XI0 + col0 + 2];
                    if (col0 + 3 < 210) v.w += g_pa[n * PAS + XI0 + col0 + 3];
                }
                *(float4*)&g_hpq[nm * OCP + col0] = v;
            }
        }
        __syncthreads();
    }
}

// ---------------- statsA: BN1 partials (0..299) + BN3 partials (300..399),
//                  last-arriving block finalizes BN1+BN3 scale/shift ----------------
__global__ __launch_bounds__(256) void k_statsA(int L,
        const float* __restrict__ g1, const float* __restrict__ b1,
        const float* __restrict__ ge, const float* __restrict__ be,
        const float* __restrict__ g3, const float* __restrict__ b3b) {
    int b = blockIdx.x, c = threadIdx.x;
    if (b < 300) {
        if (c < 210) {
            int r0 = b * 80;
            float s = 0.f, s2 = 0.f;
#pragma unroll 4
            for (int r = r0; r < r0 + 80; r++) {
                float v = g_hpq[r * OCP + c];
                s += v; s2 = fmaf(v, v, s2);
            }
            g_part[b * 512 + c] = s;
            g_part[b * 512 + 256 + c] = s2;
        }
    } else {
        if (c < 128) {
            int n0 = (b - 300) * 20;
            float sm = 0.f, sv = 0.f;
            for (int n = n0; n < n0 + 20; n++) {
                float bb = g_pa[n * PAS + WA0 + c];
                float Sp = 0.f, Sp2 = 0.f, Sq = 0.f, Sq2 = 0.f;
#pragma unroll
                for (int m = 0; m < MNB; m++) {
                    const float* row = g_hpq + (n * MNB + m) * OCP;
                    float p = row[210 + c], q = row[338 + c];
                    Sp += p; Sp2 = fmaf(p, p, Sp2); Sq += q; Sq2 = fmaf(q, q, Sq2);
                }
                sm += bb + (Sp + Sq) * (1.f / 12.f);
                sv += bb * bb + (Sp2 + Sq2) * (1.f / 12.f)
                    + 2.f * bb * (Sp + Sq) * (1.f / 12.f)
                    + 2.f * Sp * Sq * (1.f / 144.f);
            }
            g_part[b * 512 + c] = sm;
            g_part[b * 512 + 256 + c] = sv;
        }
    }
    // last-block finalize
    __shared__ int s_last;
    __threadfence();
    __syncthreads();
    if (c == 0) {
        int old = atomicAdd(&g_cnt, 1);
        s_last = (old == 399);
    }
    __syncthreads();
    if (!s_last) return;
    if (c == 0) g_cnt = 0;   // reset for next invocation (graph replay safe)
    if (c < 210) {           // BN1 finalize
        float S0 = 0.f, S1 = 0.f, T0 = 0.f, T1 = 0.f;
        for (int bb = 0; bb < 300; bb += 2) {
            S0 += g_part[bb * 512 + c];       S1 += g_part[(bb + 1) * 512 + c];
            T0 += g_part[bb * 512 + 256 + c]; T1 += g_part[(bb + 1) * 512 + 256 + c];
        }
        float m = (S0 + S1) * (1.f / 24000.f);
        float v = (T0 + T1) * (1.f / 24000.f) - m * m; if (v < 0.f) v = 0.f;
        float gm, bt;
        if (c < 128) { gm = g1[L * 128 + c]; bt = b1[L * 128 + c]; }
        else         { gm = ge[L * 82 + c - 128]; bt = be[L * 82 + c - 128]; }
        float sc = gm * rsqrtf(v + 1e-5f);
        g_bn[c] = sc;
        g_bn[256 + c] = bt - m * sc;
    }
    if (c < 128) {           // BN3 finalize
        float S0 = 0.f, S1 = 0.f, T0 = 0.f, T1 = 0.f;
        for (int bb = 300; bb < 400; bb += 2) {
            S0 += g_part[bb * 512 + c];       S1 += g_part[(bb + 1) * 512 + c];
            T0 += g_part[bb * 512 + 256 + c]; T1 += g_part[(bb + 1) * 512 + 256 + c];
        }
        float m = (S0 + S1) * (1.f / 2000.f);
        float v = (T0 + T1) * (1.f / 2000.f) - m * m; if (v < 0.f) v = 0.f;
        float sc = g3[L * 128 + c] * rsqrtf(v + 1e-5f);
        g_bn[512 + c] = sc;
        g_bn[640 + c] = b3b[L * 128 + c] - m * sc;
    }
}

// ---------------- point: eupd (b<7688) | merged two+three body (7688..8687) ----------------
__global__ __launch_bounds__(128) void k_point() {
    int b = blockIdx.x, t = threadIdx.x;
    if (b < 7688) {
        int i = b * 128 + t;
        if (i >= NEL) return;
        int nm = i / BFD, cb = i - nm * BFD;
        float z1 = fmaf(g_bn[128 + cb], g_hpq[nm * OCP + 128 + cb], g_bn[384 + cb]);
        float z2 = fmaf(g_bn[169 + cb], g_hpq[nm * OCP + 169 + cb], g_bn[425 + cb]);
        g_e[nm * EP + cb] += sigf(z1) * spf(z2);
    } else {
        // merged two-body + three-body for (n, c); writes g_total directly
        int n = (b - 7688) * 2 + (t >> 6), c = t & 63;
        float sa = g_bn[c], ta = g_bn[256 + c];
        float sb = g_bn[64 + c], tb = g_bn[320 + c];
        float sg = g_bn[512 + c], tg = g_bn[640 + c];
        float sf = g_bn[576 + c], tf = g_bn[704 + c];
        float bg = fmaf(sg, g_pa[n * PAS + WA0 + c], tg);
        float bf = fmaf(sf, g_pa[n * PAS + WA0 + 64 + c], tf);
        float acc2 = 0.f;
        float ug[12], uf[12], Evg[12], Evf[12];
#pragma unroll
        for (int m = 0; m < MNB; m++) {
            const float* row = g_hpq + (n * MNB + m) * OCP;
            float z1 = fmaf(sa, row[c], ta);
            float z2 = fmaf(sb, row[64 + c], tb);
            acc2 += sigf(z1) * spf(z2);
            ug[m] = sg * row[210 + c];
            uf[m] = sf * row[274 + c];
            Evg[m] = __expf(-sg * row[338 + c]);
            Evf[m] = __expf(sf * row[402 + c]);
        }
        float acc = 0.f;
#pragma unroll
        for (int m = 0; m < MNB; m++) {
            float Eag = __expf(-(bg + ug[m]));
            float Faf = __expf(bf + uf[m]);
#pragma unroll
            for (int l = 0; l < MNB; l++) {
                float den = fmaf(Eag, Evg[l], 1.f);
                float num = fmaf(Faf, Evf[l], 1.f);
                acc += __fdividef(__logf(num), den);
            }
        }
        g_total[n * AF + c] = acc2 + acc;
    }
}

// ---------------- BN2 partials ----------------
__global__ __launch_bounds__(64) void k_stats2_part() {
    int c = threadIdx.x;
    int r0 = blockIdx.x * 40;
    float s = 0.f, s2 = 0.f;
    for (int r = r0; r < r0 + 40; r++) {
        float v = g_total[r * AF + c];
        s += v; s2 = fmaf(v, v, s2);
    }
    g_part[blockIdx.x * 512 + c] = s;
    g_part[blockIdx.x * 512 + 64 + c] = s2;
}

// ---------------- BN2 finalize (redundant per block) + x update ----------------
__global__ __launch_bounds__(1024) void k_xupd(int L, const float* __restrict__ g2,
                                               const float* __restrict__ b2) {
    __shared__ float s_sc[64], s_sh[64];
    int t = threadIdx.x;
    if (t < 64) {
        float S = 0.f, S2 = 0.f;
        for (int b = 0; b < 50; b++) { S += g_part[b * 512 + t]; S2 += g_part[b * 512 + 64 + t]; }
        float m = S * (1.f / 2000.f);
        float v = S2 * (1.f / 2000.f) - m * m; if (v < 0.f) v = 0.f;
        float sc = g2[L * 64 + t] * rsqrtf(v + 1e-5f);
        s_sc[t] = sc;
        s_sh[t] = b2[L * 64 + t] - m * sc;
    }
    __syncthreads();
    int i = blockIdx.x * 1024 + t;
    int c = i & 63;
    float z = g_x[i] + fmaf(s_sc[c], g_total[i], s_sh[c]);
    g_x[i] = spf(z);
}

// ---------------- head: fc1 + softplus ----------------
__global__ __launch_bounds__(128) void k_fc1(const float* __restrict__ W, const float* __restrict__ b) {
    __shared__ float sx[16 * 64];
    int n0 = blockIdx.x * 16, h = threadIdx.x;
    for (int i = h; i < 1024; i += 128) sx[i] = spf(g_x[n0 * 64 + i]);
    __syncthreads();
    float acc[16]; float bb = b[h];
#pragma unroll
    for (int r = 0; r < 16; r++) acc[r] = bb;
    for (int k = 0; k < 64; k++) {
        float w = W[h * 64 + k];
#pragma unroll
        for (int r = 0; r < 16; r++) acc[r] = fmaf(sx[r * 64 + k], w, acc[r]);
    }
#pragma unroll
    for (int r = 0; r < 16; r++) g_y[(n0 + r) * 128 + h] = spf(acc[r]);
}

// ---------------- segment-mean pool + output dot ----------------
__global__ __launch_bounds__(128) void k_pool(const int* __restrict__ seg, const float* __restrict__ outW,
                                              const float* __restrict__ outb, float* __restrict__ out) {
    __shared__ int sseg[NATOM];
    __shared__ float red[128];
    int g = blockIdx.x, c = threadIdx.x;
    for (int i = c; i < NATOM; i += 128) sseg[i] = seg[i];
    __syncthreads();
    float sum = 0.f; int cnt = 0;
    for (int n = 0; n < NATOM; n++) {
        int s = sseg[n];
        if (s > g) break;
        if (s == g) { sum += g_y[n * 128 + c]; cnt++; }
    }
    red[c] = sum * outW[c];
    __syncthreads();
    for (int s = 64; s > 0; s >>= 1) {
        if (c < s) red[c] += red[c + s];
        __syncthreads();
    }
    if (c == 0) out[g] = red[0] / fmaxf((float)cnt, 1.f) + outb[0];
}

// ---------------- launch ----------------
extern "C" void kernel_launch(void* const* d_in, const int* in_sizes, int n_in,
                              void* d_out, int out_size) {
    const float* atom = (const float*)d_in[0];
    const float* nbr  = (const float*)d_in[1];
    const int*   idx  = (const int*)d_in[2];
    const int*   seg  = (const int*)d_in[3];
    const float* embW = (const float*)d_in[4];
    const float* embb = (const float*)d_in[5];
    const float* fcW  = (const float*)d_in[6];
    const float* fcb  = (const float*)d_in[7];
    const float* bn1g = (const float*)d_in[8];
    const float* bn1b = (const float*)d_in[9];
    const float* bn2g = (const float*)d_in[10];
    const float* bn2b = (const float*)d_in[11];
    const float* eW   = (const float*)d_in[12];
    const float* eb   = (const float*)d_in[13];
    const float* bneg = (const float*)d_in[14];
    const float* bneb = (const float*)d_in[15];
    const float* W3   = (const float*)d_in[16];
    const float* b3   = (const float*)d_in[17];
    const float* bn3g = (const float*)d_in[18];
    const float* bn3b = (const float*)d_in[19];
    const float* fc1W = (const float*)d_in[20];
    const float* fc1b = (const float*)d_in[21];
    const float* outW = (const float*)d_in[22];
    const float* outb = (const float*)d_in[23];
    float* out = (float*)d_out;

    const int PACK_N = 3 * KPE * WSE + 3 * KPA * PAS + 3 * PAS + 92 * 64 + NM * EP;
    k_pack<<<(PACK_N + 255) / 256, 256>>>(fcW, eW, W3, fcb, eb, b3, embW, nbr);
    k_emb<<<NATOM / 16, 64>>>(atom, embb);

    for (int L = 0; L < 3; L++) {
        k_pa<<<dim3(32, 13), dim3(16, 8)>>>(L);
        k_edge<<<dim3(75, 8), dim3(16, 8)>>>(L, idx);
        k_statsA<<<400, 256>>>(L, bn1g, bn1b, bneg, bneb, bn3g, bn3b);
        k_point<<<8688, 128>>>();
        k_stats2_part<<<50, 64>>>();
        k_xupd<<<125, 1024>>>(L, bn2g, bn2b);
    }

    k_fc1<<<NATOM / 16, 128>>>(fc1W, fc1b);
    k_pool<<<NCR, 128>>>(seg, outW, outb, out);
}